// round 4
// baseline (speedup 1.0000x reference)
#include <cuda_runtime.h>
#include <cstdint>
#include <cstddef>

// ---------------- problem constants ----------------
constexpr int Bb   = 8;
constexpr int Ll   = 128;
constexpr int Dd   = 768;
constexpr int DEP  = 64;
constexpr int POSN = 64;
constexpr int OUTN = 768;
constexpr int BI   = Bb * Ll;                       // 1024 (b,i) rows
constexpr long long R_SIZE = (long long)BI * Ll * OUTN;   // 100663296
constexpr long long OS_OFF = R_SIZE;                       // output_sum offset
constexpr long long P_OFF  = R_SIZE + (long long)BI * OUTN; // p offset
#define NEGC (-1e30f)

// ---------------- scratch (device globals; no allocs) ----------------
__device__ __align__(16) float g_A[BI * OUTN];     // A[b,i,o] = text@Wt + pos@Wp_attn + b_attn
__device__ __align__(16) float g_pd[BI * DEP];     // sum_j p * dep
__device__ float g_wt_sum[Dd];
__device__ float g_wp_sum[POSN];
__device__ float g_wd_sum[DEP];
__device__ float g_bias_out[OUTN];                 // bp + bd
__device__ float g_bsum;                           // sum(b_attn)

// ---------------- helpers ----------------
__device__ __forceinline__ float to_tf32(float x) {
    uint32_t u;
    asm("cvt.rna.tf32.f32 %0, %1;" : "=r"(u) : "f"(x));
    return __uint_as_float(u);
}
__device__ __forceinline__ void mma8(float c[4], const uint32_t a[4], const uint32_t b[2]) {
    asm volatile(
        "mma.sync.aligned.m16n8k8.row.col.f32.tf32.tf32.f32 "
        "{%0,%1,%2,%3},{%4,%5,%6,%7},{%8,%9},{%0,%1,%2,%3};\n"
        : "+f"(c[0]), "+f"(c[1]), "+f"(c[2]), "+f"(c[3])
        : "r"(a[0]), "r"(a[1]), "r"(a[2]), "r"(a[3]), "r"(b[0]), "r"(b[1]));
}

// ---------------- K0: row sums + combined bias ----------------
__global__ void k0_sums(const float* __restrict__ Wt, const float* __restrict__ Wpa,
                        const float* __restrict__ Wda, const float* __restrict__ b_attn,
                        const float* __restrict__ bd, const float* __restrict__ bp) {
    int idx = blockIdx.x * blockDim.x + threadIdx.x;
    if (idx < 768) {
        const float4* p4 = (const float4*)(Wt + (size_t)idx * 768);
        float s = 0.f;
        #pragma unroll 4
        for (int q = 0; q < 192; q++) { float4 v = p4[q]; s += v.x + v.y + v.z + v.w; }
        g_wt_sum[idx] = s;
    } else if (idx < 832) {
        int k = idx - 768;
        const float4* p4 = (const float4*)(Wpa + (size_t)k * 768);
        float s = 0.f;
        #pragma unroll 4
        for (int q = 0; q < 192; q++) { float4 v = p4[q]; s += v.x + v.y + v.z + v.w; }
        g_wp_sum[k] = s;
    } else if (idx < 896) {
        int k = idx - 832;
        const float4* p4 = (const float4*)(Wda + (size_t)k * 768);
        float s = 0.f;
        #pragma unroll 4
        for (int q = 0; q < 192; q++) { float4 v = p4[q]; s += v.x + v.y + v.z + v.w; }
        g_wd_sum[k] = s;
    } else if (idx < 1664) {
        int n = idx - 896;
        g_bias_out[n] = bp[n] + bd[n];
    } else if (idx == 1664) {
        const float4* p4 = (const float4*)b_attn;
        float s = 0.f;
        #pragma unroll 4
        for (int q = 0; q < 192; q++) { float4 v = p4[q]; s += v.x + v.y + v.z + v.w; }
        g_bsum = s;
    }
}

// ---------------- gemm_small: C[1024,768] = A1@B1 + A2@B2 + bias (+ addend) ----------------
// tf32 tensor-core GEMM. BM=64, BN=128, BK=32, 4 warps (warp tile 32x64).
// out_==nullptr -> write g_A.  bias==nullptr -> use g_bias_out.  use_pd -> A2 = g_pd.
__global__ void __launch_bounds__(128) gemm_small(
    const float* __restrict__ A1, int lda1, const float* __restrict__ B1, int K1,
    const float* __restrict__ A2_, int lda2, const float* __restrict__ B2, int K2,
    int use_pd, const float* __restrict__ bias_, const float* __restrict__ addend,
    float* __restrict__ out_) {

    __shared__ float a_sm[64 * 36];   // stride 36 (mod32==4 -> conflict-free A frags)
    __shared__ float b_sm[32 * 136];  // stride 136 (mod32==8 -> conflict-free B frags)
    __shared__ float bias_s[128];

    const int tid   = threadIdx.x;
    const int nbase = blockIdx.x * 128;
    const int mbase = blockIdx.y * 64;
    const float* A2   = use_pd ? g_pd : A2_;
    float*       out  = out_ ? out_ : g_A;
    const float* bias = bias_ ? bias_ : g_bias_out;

    bias_s[tid] = bias[nbase + tid];

    const int w  = tid >> 5, lane = tid & 31;
    const int g  = lane >> 2, t = lane & 3;
    const int wm = w >> 1, wn = w & 1;

    float acc[2][8][4];
    #pragma unroll
    for (int mf = 0; mf < 2; mf++)
        #pragma unroll
        for (int nf = 0; nf < 8; nf++)
            #pragma unroll
            for (int q = 0; q < 4; q++) acc[mf][nf][q] = 0.f;

    #pragma unroll
    for (int s = 0; s < 2; s++) {
        const float* Ap = s ? A2 : A1;
        const float* Bp = s ? B2 : B1;
        const int lda   = s ? lda2 : lda1;
        const int Ks    = s ? K2 : K1;
        for (int kt = 0; kt < Ks; kt += 32) {
            #pragma unroll
            for (int it = 0; it < 4; it++) {
                int idx = tid + it * 128;
                int row = idx >> 3, k4 = idx & 7;
                float4 v = *(const float4*)(Ap + (size_t)(mbase + row) * lda + kt + k4 * 4);
                float4 wv = make_float4(to_tf32(v.x), to_tf32(v.y), to_tf32(v.z), to_tf32(v.w));
                *(float4*)(a_sm + row * 36 + k4 * 4) = wv;
            }
            #pragma unroll
            for (int it = 0; it < 8; it++) {
                int idx = tid + it * 128;
                int kr = idx >> 5, c4 = idx & 31;
                float4 v = *(const float4*)(Bp + (size_t)(kt + kr) * 768 + nbase + c4 * 4);
                float4 wv = make_float4(to_tf32(v.x), to_tf32(v.y), to_tf32(v.z), to_tf32(v.w));
                *(float4*)(b_sm + kr * 136 + c4 * 4) = wv;
            }
            __syncthreads();
            #pragma unroll
            for (int ks = 0; ks < 4; ks++) {
                const int kb = ks * 8;
                uint32_t a[2][4], b[8][2];
                #pragma unroll
                for (int mf = 0; mf < 2; mf++) {
                    int r = wm * 32 + mf * 16 + g;
                    a[mf][0] = __float_as_uint(a_sm[r * 36 + kb + t]);
                    a[mf][1] = __float_as_uint(a_sm[(r + 8) * 36 + kb + t]);
                    a[mf][2] = __float_as_uint(a_sm[r * 36 + kb + 4 + t]);
                    a[mf][3] = __float_as_uint(a_sm[(r + 8) * 36 + kb + 4 + t]);
                }
                #pragma unroll
                for (int nf = 0; nf < 8; nf++) {
                    int c = wn * 64 + nf * 8 + g;
                    b[nf][0] = __float_as_uint(b_sm[(kb + t) * 136 + c]);
                    b[nf][1] = __float_as_uint(b_sm[(kb + 4 + t) * 136 + c]);
                }
                #pragma unroll
                for (int mf = 0; mf < 2; mf++)
                    #pragma unroll
                    for (int nf = 0; nf < 8; nf++) mma8(acc[mf][nf], a[mf], b[nf]);
            }
            __syncthreads();
        }
    }

    // epilogue
    #pragma unroll
    for (int mf = 0; mf < 2; mf++) {
        #pragma unroll
        for (int nf = 0; nf < 8; nf++) {
            int r0 = mbase + wm * 32 + mf * 16 + g;
            int cl = wn * 64 + nf * 8 + 2 * t;
            int c  = nbase + cl;
            float a0 = 0.f, a1 = 0.f, a2 = 0.f, a3 = 0.f;
            if (addend) {
                a0 = addend[(size_t)r0 * 768 + c];
                a1 = addend[(size_t)r0 * 768 + c + 1];
                a2 = addend[(size_t)(r0 + 8) * 768 + c];
                a3 = addend[(size_t)(r0 + 8) * 768 + c + 1];
            }
            float2 v0 = make_float2(acc[mf][nf][0] + bias_s[cl] + a0,
                                    acc[mf][nf][1] + bias_s[cl + 1] + a1);
            float2 v1 = make_float2(acc[mf][nf][2] + bias_s[cl] + a2,
                                    acc[mf][nf][3] + bias_s[cl + 1] + a3);
            *(float2*)(out + (size_t)r0 * 768 + c) = v0;
            *(float2*)(out + (size_t)(r0 + 8) * 768 + c) = v1;
        }
    }
}

// ---------------- kernel S: scores + softmax + p + p-weighted dep ----------------
// one block per (b,i), 128 threads (one per j). All in exact fp32.
__global__ void __launch_bounds__(128) kernel_s(
    const float* __restrict__ text, const int* __restrict__ adj,
    const float* __restrict__ dep, const float* __restrict__ pos,
    float* __restrict__ p_out) {

    __shared__ float dep_s[128 * 65];  // stride 65 -> conflict-free column reads
    __shared__ float ws_s[64];
    __shared__ float p_s[128];
    __shared__ float red[128];

    const int bi = blockIdx.x;
    const int tid = threadIdx.x;

    if (tid < 64) ws_s[tid] = g_wd_sum[tid];

    // s_base = text . wt_sum + pos . wp_sum + sum(b_attn)
    float ps = 0.f;
    #pragma unroll
    for (int d = tid; d < 768; d += 128) ps += text[(size_t)bi * 768 + d] * g_wt_sum[d];
    if (tid < 64) ps += pos[(size_t)bi * 64 + tid] * g_wp_sum[tid];
    red[tid] = ps;
    __syncthreads();
    for (int off = 64; off > 0; off >>= 1) {
        if (tid < off) red[tid] += red[tid + off];
        __syncthreads();
    }
    const float s_base = red[0] + g_bsum;
    __syncthreads();

    // per-j score = s_base + dep[j] . wd_sum  (+ mask); also stage dep in smem
    const float4* dr = (const float4*)(dep + ((size_t)bi * 128 + tid) * 64);
    float dot = 0.f;
    #pragma unroll
    for (int q = 0; q < 16; q++) {
        float4 v = dr[q];
        dot += v.x * ws_s[4 * q] + v.y * ws_s[4 * q + 1] + v.z * ws_s[4 * q + 2] + v.w * ws_s[4 * q + 3];
        int base = tid * 65 + 4 * q;
        dep_s[base]     = v.x;
        dep_s[base + 1] = v.y;
        dep_s[base + 2] = v.z;
        dep_s[base + 3] = v.w;
    }
    float score = s_base + dot + (adj[(size_t)bi * 128 + tid] == 0 ? NEGC : 0.f);

    // softmax over 128 j's
    red[tid] = score;
    __syncthreads();
    for (int off = 64; off > 0; off >>= 1) {
        if (tid < off) red[tid] = fmaxf(red[tid], red[tid + off]);
        __syncthreads();
    }
    const float mx = red[0];
    __syncthreads();
    const float e = expf(score - mx);
    red[tid] = e;
    __syncthreads();
    for (int off = 64; off > 0; off >>= 1) {
        if (tid < off) red[tid] += red[tid + off];
        __syncthreads();
    }
    const float Z = red[0];
    const float p = e / Z;
    p_s[tid] = p;
    p_out[(size_t)bi * 128 + tid] = p;
    __syncthreads();

    // pd[k] = sum_j p_j * dep[j][k]  (split j-range across two thread halves)
    const int half = tid >> 6, k = tid & 63;
    float s = 0.f;
    #pragma unroll 4
    for (int j = half * 64; j < half * 64 + 64; j++) s += p_s[j] * dep_s[j * 65 + k];
    red[tid] = s;
    __syncthreads();
    if (tid < 64) g_pd[(size_t)bi * 64 + tid] = red[tid] + red[tid + 64];
}

// ---------------- kernel R: r = dep @ Wd_attn + A  (the big one) ----------------
// one CTA = one (b,i) (M=128 rows of j) x 256-col N-tile; K=64 entirely in smem.
// dep stride 68 floats (mod32==4) and Wd stride 264 (mod32==8) -> conflict-free frags.
constexpr int R_DEPS  = 128 * 68;           // 8704 floats
constexpr int R_WDS   = 64 * 264;           // 16896 floats
constexpr int R_SMEMF = R_DEPS + R_WDS + 256;
constexpr int R_SMEMB = R_SMEMF * 4;        // 103424 bytes

__global__ void __launch_bounds__(256, 1) kernel_r(
    const float* __restrict__ dep, const float* __restrict__ Wda,
    float* __restrict__ rout) {

    extern __shared__ float sm[];
    float* dep_s = sm;
    float* wd_s  = sm + R_DEPS;
    float* a_s   = sm + R_DEPS + R_WDS;

    const int tid = threadIdx.x;
    const int nt  = blockIdx.x;   // 0..2
    const int bi  = blockIdx.y;   // 0..1023

    a_s[tid] = g_A[(size_t)bi * 768 + nt * 256 + tid];

    // dep tile [128 x 64] (contiguous block)
    const float4* db4 = (const float4*)(dep + (size_t)bi * 128 * 64);
    #pragma unroll
    for (int it = 0; it < 8; it++) {
        int idx = tid + it * 256;
        int j = idx >> 4, k4 = idx & 15;
        float4 v = db4[idx];
        float4 wv = make_float4(to_tf32(v.x), to_tf32(v.y), to_tf32(v.z), to_tf32(v.w));
        *(float4*)(dep_s + j * 68 + k4 * 4) = wv;
    }
    // Wd_attn slice [64 x 256]
    #pragma unroll
    for (int it = 0; it < 16; it++) {
        int idx = tid + it * 256;
        int k = idx >> 6, c4 = idx & 63;
        float4 v = *(const float4*)(Wda + (size_t)k * 768 + nt * 256 + c4 * 4);
        float4 wv = make_float4(to_tf32(v.x), to_tf32(v.y), to_tf32(v.z), to_tf32(v.w));
        *(float4*)(wd_s + k * 264 + c4 * 4) = wv;
    }
    __syncthreads();

    const int w  = tid >> 5, lane = tid & 31;
    const int g  = lane >> 2, t = lane & 3;
    const int wm = w >> 2, wn = w & 3;  // 2 x 4 warps; warp tile 64 x 64

    float acc[4][8][4];
    #pragma unroll
    for (int mf = 0; mf < 4; mf++)
        #pragma unroll
        for (int nf = 0; nf < 8; nf++)
            #pragma unroll
            for (int q = 0; q < 4; q++) acc[mf][nf][q] = 0.f;

    #pragma unroll
    for (int ks = 0; ks < 8; ks++) {
        const int kb = ks * 8;
        uint32_t a[4][4], b[8][2];
        #pragma unroll
        for (int mf = 0; mf < 4; mf++) {
            int r = wm * 64 + mf * 16 + g;
            a[mf][0] = __float_as_uint(dep_s[r * 68 + kb + t]);
            a[mf][1] = __float_as_uint(dep_s[(r + 8) * 68 + kb + t]);
            a[mf][2] = __float_as_uint(dep_s[r * 68 + kb + 4 + t]);
            a[mf][3] = __float_as_uint(dep_s[(r + 8) * 68 + kb + 4 + t]);
        }
        #pragma unroll
        for (int nf = 0; nf < 8; nf++) {
            int c = wn * 64 + nf * 8 + g;
            b[nf][0] = __float_as_uint(wd_s[(kb + t) * 264 + c]);
            b[nf][1] = __float_as_uint(wd_s[(kb + 4 + t) * 264 + c]);
        }
        #pragma unroll
        for (int mf = 0; mf < 4; mf++)
            #pragma unroll
            for (int nf = 0; nf < 8; nf++) mma8(acc[mf][nf], a[mf], b[nf]);
    }

    // epilogue: + A[bi, col], store (32B-sector-aligned float2 pairs)
    float* rbase = rout + (size_t)bi * 128 * 768 + nt * 256;
    #pragma unroll
    for (int mf = 0; mf < 4; mf++) {
        #pragma unroll
        for (int nf = 0; nf < 8; nf++) {
            int r0 = wm * 64 + mf * 16 + g;
            int cl = wn * 64 + nf * 8 + 2 * t;
            float2 v0 = make_float2(acc[mf][nf][0] + a_s[cl], acc[mf][nf][1] + a_s[cl + 1]);
            float2 v1 = make_float2(acc[mf][nf][2] + a_s[cl], acc[mf][nf][3] + a_s[cl + 1]);
            *(float2*)(rbase + (size_t)r0 * 768 + cl) = v0;
            *(float2*)(rbase + (size_t)(r0 + 8) * 768 + cl) = v1;
        }
    }
}

// ---------------- launch ----------------
extern "C" void kernel_launch(void* const* d_in, const int* in_sizes, int n_in,
                              void* d_out, int out_size) {
    const float* text = (const float*)d_in[0];
    const int*   adj  = (const int*)d_in[1];
    const float* dep  = (const float*)d_in[2];
    const float* pos  = (const float*)d_in[3];
    const float* Wt   = (const float*)d_in[4];
    const float* Wpa  = (const float*)d_in[5];
    const float* Wda  = (const float*)d_in[6];
    const float* ba   = (const float*)d_in[7];
    const float* Wd   = (const float*)d_in[8];
    const float* bd   = (const float*)d_in[9];
    const float* Wp   = (const float*)d_in[10];
    const float* bp   = (const float*)d_in[11];
    float* out = (float*)d_out;

    cudaFuncSetAttribute(kernel_r, cudaFuncAttributeMaxDynamicSharedMemorySize, R_SMEMB);

    // 1) row sums + combined bias
    k0_sums<<<7, 256>>>(Wt, Wpa, Wda, ba, bd, bp);
    // 2) A = text@Wt + pos@Wp_attn + b_attn  -> g_A
    gemm_small<<<dim3(6, 16), 128>>>(text, 768, Wt, 768, pos, 64, Wpa, 64,
                                     /*use_pd=*/0, ba, nullptr, nullptr);
    // 3) scores/softmax -> p (out) and g_pd
    kernel_s<<<BI, 128>>>(text, adj, dep, pos, out + P_OFF);
    // 4) r = dep@Wd_attn + A  -> out[0 : R_SIZE)
    kernel_r<<<dim3(3, BI), 256, R_SMEMB>>>(dep, Wda, out);
    // 5) output_sum = pos@Wp + g_pd@Wd + (bp+bd) + text -> out[OS_OFF : )
    gemm_small<<<dim3(6, 16), 128>>>(pos, 64, Wp, 64, nullptr, 64, Wd, 64,
                                     /*use_pd=*/1, nullptr, text, out + OS_OFF);
}

// round 6
// speedup vs baseline: 1.5293x; 1.5293x over previous
#include <cuda_runtime.h>
#include <cstdint>
#include <cstddef>

// ---------------- problem constants ----------------
constexpr int Bb   = 8;
constexpr int Ll   = 128;
constexpr int Dd   = 768;
constexpr int DEP  = 64;
constexpr int POSN = 64;
constexpr int OUTN = 768;
constexpr int BI   = Bb * Ll;                       // 1024 (b,i) rows
constexpr long long R_SIZE = (long long)BI * Ll * OUTN;   // 100663296
constexpr long long OS_OFF = R_SIZE;                       // output_sum offset
constexpr long long P_OFF  = R_SIZE + (long long)BI * OUTN; // p offset
#define NEGC (-1e30f)

// ---------------- scratch (device globals; no allocs) ----------------
__device__ __align__(16) float g_A[BI * OUTN];     // A[b,i,o] = text@Wt + pos@Wp_attn + b_attn
__device__ __align__(16) float g_pd[BI * DEP];     // sum_j p * dep
__device__ float g_wt_sum[Dd];
__device__ float g_wp_sum[POSN];
__device__ float g_wd_sum[DEP];
__device__ float g_bias_out[OUTN];                 // bp + bd
__device__ float g_bsum;                           // sum(b_attn)

// ---------------- helpers ----------------
__device__ __forceinline__ float to_tf32(float x) {
    uint32_t u;
    asm("cvt.rna.tf32.f32 %0, %1;" : "=r"(u) : "f"(x));
    return __uint_as_float(u);
}
__device__ __forceinline__ void mma8(float c[4], const uint32_t a[4], const uint32_t b[2]) {
    asm volatile(
        "mma.sync.aligned.m16n8k8.row.col.f32.tf32.tf32.f32 "
        "{%0,%1,%2,%3},{%4,%5,%6,%7},{%8,%9},{%0,%1,%2,%3};\n"
        : "+f"(c[0]), "+f"(c[1]), "+f"(c[2]), "+f"(c[3])
        : "r"(a[0]), "r"(a[1]), "r"(a[2]), "r"(a[3]), "r"(b[0]), "r"(b[1]));
}

// ---------------- K0: row sums + combined bias (warp-per-row) ----------------
// tasks: warp 0..767 -> Wt row sums; 768..831 -> Wpa; 832..895 -> Wda;
//        896 -> sum(b_attn); 897..920 -> bias_out (lane-per-elem).
__global__ void k0_sums(const float* __restrict__ Wt, const float* __restrict__ Wpa,
                        const float* __restrict__ Wda, const float* __restrict__ b_attn,
                        const float* __restrict__ bd, const float* __restrict__ bp) {
    const int gw   = (blockIdx.x * blockDim.x + threadIdx.x) >> 5;
    const int lane = threadIdx.x & 31;
    if (gw <= 896) {
        const float* src;
        if (gw < 768)      src = Wt  + (size_t)gw * 768;
        else if (gw < 832) src = Wpa + (size_t)(gw - 768) * 768;
        else if (gw < 896) src = Wda + (size_t)(gw - 832) * 768;
        else               src = b_attn;
        const float4* p4 = (const float4*)src;
        float s = 0.f;
        #pragma unroll
        for (int i = 0; i < 6; i++) { float4 v = p4[lane + i * 32]; s += v.x + v.y + v.z + v.w; }
        #pragma unroll
        for (int o = 16; o; o >>= 1) s += __shfl_xor_sync(0xffffffffu, s, o);
        if (lane == 0) {
            if (gw < 768)      g_wt_sum[gw] = s;
            else if (gw < 832) g_wp_sum[gw - 768] = s;
            else if (gw < 896) g_wd_sum[gw - 832] = s;
            else               g_bsum = s;
        }
    } else if (gw >= 897 && gw < 921) {
        int n = (gw - 897) * 32 + lane;
        g_bias_out[n] = bp[n] + bd[n];
    }
}

// ---------------- gemm_small: C[1024,768] = A1@B1 + A2@B2 + bias (+ addend) ----------------
// tf32 tensor-core GEMM. BM=64, BN=128, BK=32, 4 warps (warp tile 32x64).
__global__ void __launch_bounds__(128) gemm_small(
    const float* __restrict__ A1, int lda1, const float* __restrict__ B1, int K1,
    const float* __restrict__ A2_, int lda2, const float* __restrict__ B2, int K2,
    int use_pd, const float* __restrict__ bias_, const float* __restrict__ addend,
    float* __restrict__ out_) {

    __shared__ float a_sm[64 * 36];
    __shared__ float b_sm[32 * 136];
    __shared__ float bias_s[128];

    const int tid   = threadIdx.x;
    const int nbase = blockIdx.x * 128;
    const int mbase = blockIdx.y * 64;
    const float* A2   = use_pd ? g_pd : A2_;
    float*       out  = out_ ? out_ : g_A;
    const float* bias = bias_ ? bias_ : g_bias_out;

    bias_s[tid] = bias[nbase + tid];

    const int w  = tid >> 5, lane = tid & 31;
    const int g  = lane >> 2, t = lane & 3;
    const int wm = w >> 1, wn = w & 1;

    float acc[2][8][4];
    #pragma unroll
    for (int mf = 0; mf < 2; mf++)
        #pragma unroll
        for (int nf = 0; nf < 8; nf++)
            #pragma unroll
            for (int q = 0; q < 4; q++) acc[mf][nf][q] = 0.f;

    #pragma unroll
    for (int s = 0; s < 2; s++) {
        const float* Ap = s ? A2 : A1;
        const float* Bp = s ? B2 : B1;
        const int lda   = s ? lda2 : lda1;
        const int Ks    = s ? K2 : K1;
        for (int kt = 0; kt < Ks; kt += 32) {
            #pragma unroll
            for (int it = 0; it < 4; it++) {
                int idx = tid + it * 128;
                int row = idx >> 3, k4 = idx & 7;
                float4 v = *(const float4*)(Ap + (size_t)(mbase + row) * lda + kt + k4 * 4);
                float4 wv = make_float4(to_tf32(v.x), to_tf32(v.y), to_tf32(v.z), to_tf32(v.w));
                *(float4*)(a_sm + row * 36 + k4 * 4) = wv;
            }
            #pragma unroll
            for (int it = 0; it < 8; it++) {
                int idx = tid + it * 128;
                int kr = idx >> 5, c4 = idx & 31;
                float4 v = *(const float4*)(Bp + (size_t)(kt + kr) * 768 + nbase + c4 * 4);
                float4 wv = make_float4(to_tf32(v.x), to_tf32(v.y), to_tf32(v.z), to_tf32(v.w));
                *(float4*)(b_sm + kr * 136 + c4 * 4) = wv;
            }
            __syncthreads();
            #pragma unroll
            for (int ks = 0; ks < 4; ks++) {
                const int kb = ks * 8;
                uint32_t a[2][4], b[8][2];
                #pragma unroll
                for (int mf = 0; mf < 2; mf++) {
                    int r = wm * 32 + mf * 16 + g;
                    a[mf][0] = __float_as_uint(a_sm[r * 36 + kb + t]);
                    a[mf][1] = __float_as_uint(a_sm[(r + 8) * 36 + kb + t]);
                    a[mf][2] = __float_as_uint(a_sm[r * 36 + kb + 4 + t]);
                    a[mf][3] = __float_as_uint(a_sm[(r + 8) * 36 + kb + 4 + t]);
                }
                #pragma unroll
                for (int nf = 0; nf < 8; nf++) {
                    int c = wn * 64 + nf * 8 + g;
                    b[nf][0] = __float_as_uint(b_sm[(kb + t) * 136 + c]);
                    b[nf][1] = __float_as_uint(b_sm[(kb + 4 + t) * 136 + c]);
                }
                #pragma unroll
                for (int mf = 0; mf < 2; mf++)
                    #pragma unroll
                    for (int nf = 0; nf < 8; nf++) mma8(acc[mf][nf], a[mf], b[nf]);
            }
            __syncthreads();
        }
    }

    #pragma unroll
    for (int mf = 0; mf < 2; mf++) {
        #pragma unroll
        for (int nf = 0; nf < 8; nf++) {
            int r0 = mbase + wm * 32 + mf * 16 + g;
            int cl = wn * 64 + nf * 8 + 2 * t;
            int c  = nbase + cl;
            float a0 = 0.f, a1 = 0.f, a2 = 0.f, a3 = 0.f;
            if (addend) {
                a0 = addend[(size_t)r0 * 768 + c];
                a1 = addend[(size_t)r0 * 768 + c + 1];
                a2 = addend[(size_t)(r0 + 8) * 768 + c];
                a3 = addend[(size_t)(r0 + 8) * 768 + c + 1];
            }
            float2 v0 = make_float2(acc[mf][nf][0] + bias_s[cl] + a0,
                                    acc[mf][nf][1] + bias_s[cl + 1] + a1);
            float2 v1 = make_float2(acc[mf][nf][2] + bias_s[cl] + a2,
                                    acc[mf][nf][3] + bias_s[cl + 1] + a3);
            *(float2*)(out + (size_t)r0 * 768 + c) = v0;
            *(float2*)(out + (size_t)(r0 + 8) * 768 + c) = v1;
        }
    }
}

// ---------------- kernel S: scores + softmax + p + p-weighted dep ----------------
__global__ void __launch_bounds__(128) kernel_s(
    const float* __restrict__ text, const int* __restrict__ adj,
    const float* __restrict__ dep, const float* __restrict__ pos,
    float* __restrict__ p_out) {

    __shared__ float dep_s[128 * 65];
    __shared__ float ws_s[64];
    __shared__ float p_s[128];
    __shared__ float red[128];

    const int bi  = blockIdx.x;
    const int tid = threadIdx.x;
    const int lane = tid & 31;

    if (tid < 64) ws_s[tid] = g_wd_sum[tid];

    // s_base = text . wt_sum + pos . wp_sum + sum(b_attn)
    float ps = 0.f;
    #pragma unroll
    for (int d = tid; d < 768; d += 128) ps += text[(size_t)bi * 768 + d] * g_wt_sum[d];
    if (tid < 64) ps += pos[(size_t)bi * 64 + tid] * g_wp_sum[tid];
    #pragma unroll
    for (int o = 16; o; o >>= 1) ps += __shfl_xor_sync(0xffffffffu, ps, o);
    if (lane == 0) red[tid >> 5] = ps;
    __syncthreads();
    const float s_base = red[0] + red[1] + red[2] + red[3] + g_bsum;
    __syncthreads();

    // per-j score = s_base + dep[j].wd_sum (+ mask); stage dep in smem
    const float4* dr = (const float4*)(dep + ((size_t)bi * 128 + tid) * 64);
    float dot = 0.f;
    #pragma unroll
    for (int q = 0; q < 16; q++) {
        float4 v = dr[q];
        dot += v.x * ws_s[4 * q] + v.y * ws_s[4 * q + 1] + v.z * ws_s[4 * q + 2] + v.w * ws_s[4 * q + 3];
        int base = tid * 65 + 4 * q;
        dep_s[base]     = v.x;
        dep_s[base + 1] = v.y;
        dep_s[base + 2] = v.z;
        dep_s[base + 3] = v.w;
    }
    const float score = s_base + dot + (adj[(size_t)bi * 128 + tid] == 0 ? NEGC : 0.f);

    // max
    float m = score;
    #pragma unroll
    for (int o = 16; o; o >>= 1) m = fmaxf(m, __shfl_xor_sync(0xffffffffu, m, o));
    if (lane == 0) red[tid >> 5] = m;
    __syncthreads();
    const float mx = fmaxf(fmaxf(red[0], red[1]), fmaxf(red[2], red[3]));
    __syncthreads();
    // sum
    const float e = expf(score - mx);
    float z = e;
    #pragma unroll
    for (int o = 16; o; o >>= 1) z += __shfl_xor_sync(0xffffffffu, z, o);
    if (lane == 0) red[tid >> 5] = z;
    __syncthreads();
    const float Z = red[0] + red[1] + red[2] + red[3];
    const float p = e / Z;
    p_s[tid] = p;
    p_out[(size_t)bi * 128 + tid] = p;
    __syncthreads();

    // pd[k] = sum_j p_j * dep[j][k]
    const int half = tid >> 6, k = tid & 63;
    float s = 0.f;
    #pragma unroll 4
    for (int j = half * 64; j < half * 64 + 64; j++) s += p_s[j] * dep_s[j * 65 + k];
    red[tid] = s;
    __syncthreads();
    if (tid < 64) g_pd[(size_t)bi * 64 + tid] = red[tid] + red[tid + 64];
}

// ---------------- kernel R: r = dep @ Wd_attn + A  (persistent over bi) ----------------
// grid (3, 49) = 147 CTAs (one wave). Each CTA: fixed N-tile (256 cols), loads its
// Wd_attn slice ONCE (column-permuted so the epilogue is pure STG.128), then loops
// over bi with register prefetch of the next dep tile + A row.
constexpr int SD     = 68;                // dep_s row stride (mod32==4, conflict-free A frags)
constexpr int SB     = 264;               // wd_s row stride (mod32==8, conflict-free B frags)
constexpr int R_DEPS = 128 * SD;          // 8704 floats
constexpr int R_WDS  = 64 * SB;           // 16896 floats
constexpr int R_SMEMB = (R_DEPS + R_WDS + 256) * 4;  // 103424 bytes
constexpr int NCH    = 49;                // bi chunks

__global__ void __launch_bounds__(256, 1) kernel_r(
    const float* __restrict__ dep, const float* __restrict__ Wda,
    float* __restrict__ rout) {

    extern __shared__ float sm[];
    float* dep_s = sm;
    float* wd_s  = sm + R_DEPS;
    float* a_s   = sm + R_DEPS + R_WDS;

    const int tid = threadIdx.x;
    const int nt  = blockIdx.x;   // 0..2 N-tile

    // Wd_attn slice [64 x 256], stored with a within-16 column permutation:
    // actual col A = 16q + 4T + d  ->  logical L = 16q + 8*(d>>1) + 2T + (d&1).
    // This makes each thread's 4 accumulator values land on 4 consecutive actual cols.
    #pragma unroll
    for (int it = 0; it < 16; it++) {
        int idx = tid + it * 256;
        int k = idx >> 6, c4 = idx & 63;
        float4 v = *(const float4*)(Wda + (size_t)k * 768 + nt * 256 + c4 * 4);
        int A  = c4 * 4;
        int L0 = (A & ~15) + (((A >> 2) & 3) << 1);
        *(float2*)(wd_s + k * SB + L0)     = make_float2(to_tf32(v.x), to_tf32(v.y));
        *(float2*)(wd_s + k * SB + L0 + 8) = make_float2(to_tf32(v.z), to_tf32(v.w));
    }

    const int w  = tid >> 5, lane = tid & 31;
    const int g  = lane >> 2, t = lane & 3;
    const int wm = w >> 2, wn = w & 3;   // 2 x 4 warps; warp tile 64 x 64

    int bi = blockIdx.y;                 // 0..48, strided by NCH

    // prefetch first dep tile + A row into registers
    float4 pf[8];
    float  pfa;
    {
        const float4* db4 = (const float4*)(dep + (size_t)bi * 8192);
        #pragma unroll
        for (int it = 0; it < 8; it++) pf[it] = db4[tid + it * 256];
        pfa = g_A[(size_t)bi * 768 + nt * 256 + tid];
    }

    while (true) {
        __syncthreads();   // prior iteration's consumers done (first iter: wd_s ready)
        #pragma unroll
        for (int it = 0; it < 8; it++) {
            int idx = tid + it * 256;
            int j = idx >> 4, k4 = idx & 15;
            float4 v = pf[it];
            *(float4*)(dep_s + j * SD + k4 * 4) =
                make_float4(to_tf32(v.x), to_tf32(v.y), to_tf32(v.z), to_tf32(v.w));
        }
        a_s[tid] = pfa;
        __syncthreads();

        // prefetch next bi (hidden under mma + stores)
        const int bin = bi + NCH;
        if (bin < 1024) {
            const float4* db4 = (const float4*)(dep + (size_t)bin * 8192);
            #pragma unroll
            for (int it = 0; it < 8; it++) pf[it] = db4[tid + it * 256];
            pfa = g_A[(size_t)bin * 768 + nt * 256 + tid];
        }

        float acc[4][8][4];
        #pragma unroll
        for (int mf = 0; mf < 4; mf++)
            #pragma unroll
            for (int nf = 0; nf < 8; nf++)
                #pragma unroll
                for (int q = 0; q < 4; q++) acc[mf][nf][q] = 0.f;

        #pragma unroll
        for (int ks = 0; ks < 8; ks++) {
            const int kb = ks * 8;
            uint32_t a[4][4], b[8][2];
            #pragma unroll
            for (int mf = 0; mf < 4; mf++) {
                int r = wm * 64 + mf * 16 + g;
                a[mf][0] = __float_as_uint(dep_s[r * SD + kb + t]);
                a[mf][1] = __float_as_uint(dep_s[(r + 8) * SD + kb + t]);
                a[mf][2] = __float_as_uint(dep_s[r * SD + kb + 4 + t]);
                a[mf][3] = __float_as_uint(dep_s[(r + 8) * SD + kb + 4 + t]);
            }
            #pragma unroll
            for (int nf = 0; nf < 8; nf++) {
                int c = wn * 64 + nf * 8 + g;   // logical column
                b[nf][0] = __float_as_uint(wd_s[(kb + t) * SB + c]);
                b[nf][1] = __float_as_uint(wd_s[(kb + 4 + t) * SB + c]);
            }
            #pragma unroll
            for (int mf = 0; mf < 4; mf++)
                #pragma unroll
                for (int nf = 0; nf < 8; nf++) mma8(acc[mf][nf], a[mf], b[nf]);
        }

        // epilogue: +A, STG.128 streaming stores on actual (de-permuted) columns
        float* rbase = rout + (size_t)bi * 98304 + nt * 256;
        #pragma unroll
        for (int mf = 0; mf < 4; mf++) {
            #pragma unroll
            for (int q2 = 0; q2 < 4; q2++) {
                int r0  = wm * 64 + mf * 16 + g;
                int col = wn * 64 + (q2 << 4) + 4 * t;
                float4 a4 = *(float4*)(a_s + col);
                float4 w0 = make_float4(acc[mf][2 * q2][0] + a4.x, acc[mf][2 * q2][1] + a4.y,
                                        acc[mf][2 * q2 + 1][0] + a4.z, acc[mf][2 * q2 + 1][1] + a4.w);
                float4 w1 = make_float4(acc[mf][2 * q2][2] + a4.x, acc[mf][2 * q2][3] + a4.y,
                                        acc[mf][2 * q2 + 1][2] + a4.z, acc[mf][2 * q2 + 1][3] + a4.w);
                __stcs((float4*)(rbase + (size_t)r0 * 768 + col), w0);
                __stcs((float4*)(rbase + (size_t)(r0 + 8) * 768 + col), w1);
            }
        }

        bi = bin;
        if (bi >= 1024) break;
    }
}

// ---------------- launch ----------------
extern "C" void kernel_launch(void* const* d_in, const int* in_sizes, int n_in,
                              void* d_out, int out_size) {
    const float* text = (const float*)d_in[0];
    const int*   adj  = (const int*)d_in[1];
    const float* dep  = (const float*)d_in[2];
    const float* pos  = (const float*)d_in[3];
    const float* Wt   = (const float*)d_in[4];
    const float* Wpa  = (const float*)d_in[5];
    const float* Wda  = (const float*)d_in[6];
    const float* ba   = (const float*)d_in[7];
    const float* Wd   = (const float*)d_in[8];
    const float* bd   = (const float*)d_in[9];
    const float* Wp   = (const float*)d_in[10];
    const float* bp   = (const float*)d_in[11];
    float* out = (float*)d_out;

    cudaFuncSetAttribute(kernel_r, cudaFuncAttributeMaxDynamicSharedMemorySize, R_SMEMB);

    // 1) row sums + combined bias (921 warp-tasks -> 116 blocks x 8 warps)
    k0_sums<<<116, 256>>>(Wt, Wpa, Wda, ba, bd, bp);
    // 2) A = text@Wt + pos@Wp_attn + b_attn  -> g_A
    gemm_small<<<dim3(6, 16), 128>>>(text, 768, Wt, 768, pos, 64, Wpa, 64,
                                     /*use_pd=*/0, ba, nullptr, nullptr);
    // 3) scores/softmax -> p (out) and g_pd
    kernel_s<<<BI, 128>>>(text, adj, dep, pos, out + P_OFF);
    // 4) r = dep@Wd_attn + A  -> out[0 : R_SIZE)   (persistent, one wave)
    kernel_r<<<dim3(3, NCH), 256, R_SMEMB>>>(dep, Wda, out);
    // 5) output_sum = pos@Wp + g_pd@Wd + (bp+bd) + text -> out[OS_OFF : )
    gemm_small<<<dim3(6, 16), 128>>>(pos, 64, Wp, 64, nullptr, 64, Wd, 64,
                                     /*use_pd=*/1, nullptr, text, out + OS_OFF);
}